// round 16
// baseline (speedup 1.0000x reference)
#include <cuda_runtime.h>
#include <cuda_bf16.h>
#include <cuda_fp8.h>
#include <cstdint>

// ---------------- problem dims ----------------
#define M_TOTAL 8192
#define N_TOTAL 4096
#define K_TOTAL 4096
#define FP8_MAX_F 448.0f

// ---------------- GEMM tiling ----------------
#define TILE_M 128
#define TILE_N 128
#define KC 64                       // bf16 per K-stage => 128 bytes per row
#define STAGES 3
#define KITERS (K_TOTAL / KC)       // 64
#define GEMM_THREADS 256

#define A_BYTES (TILE_M * 128)              // 16384
#define B_BYTES (TILE_N * 128)              // 16384
#define STAGE_BYTES (A_BYTES + B_BYTES)     // 32768
#define SMEM_TOTAL (STAGES * STAGE_BYTES)   // 98304

// absmax/quant grids: x has 8M float4, W has 4M float4 -> 2:1 block split
#define PRE_BLOCKS 1184
#define X_BLOCKS 790
#define X_N4 ((M_TOTAL * K_TOTAL) / 4)
#define W_N4 ((N_TOTAL * K_TOTAL) / 4)

// ---------------- device scratch ----------------
__device__ unsigned g_absmax_bits[2];                          // [0]=x, [1]=W
__device__ __nv_bfloat16 g_xq[(size_t)M_TOTAL * K_TOTAL];      // 64 MB
__device__ __nv_bfloat16 g_wq[(size_t)N_TOTAL * K_TOTAL];      // 32 MB

// ---------------- helpers ----------------
__device__ __forceinline__ uint32_t smem_u32(const void* p) {
    uint32_t a;
    asm("{ .reg .u64 t; cvta.to.shared.u64 t, %1; cvt.u32.u64 %0, t; }" : "=r"(a) : "l"(p));
    return a;
}

#define SWZ(o) ((o) ^ (((o) >> 3) & 0x70))

__device__ __forceinline__ void cp16(uint32_t dst, const void* src) {
    asm volatile("cp.async.cg.shared.global [%0], [%1], 16;" :: "r"(dst), "l"(src));
}
__device__ __forceinline__ void cp_commit() {
    asm volatile("cp.async.commit_group;" ::: "memory");
}
template <int N>
__device__ __forceinline__ void cp_wait() {
    asm volatile("cp.async.wait_group %0;" :: "n"(N) : "memory");
}

__device__ __forceinline__ void ldsm_x4(uint32_t* r, uint32_t addr) {
    asm volatile("ldmatrix.sync.aligned.m8n8.x4.shared.b16 {%0,%1,%2,%3}, [%4];"
                 : "=r"(r[0]), "=r"(r[1]), "=r"(r[2]), "=r"(r[3]) : "r"(addr));
}

__device__ __forceinline__ void mma_bf16(float* c, const uint32_t* a, const uint32_t* b) {
    asm volatile(
        "mma.sync.aligned.m16n8k16.row.col.f32.bf16.bf16.f32 "
        "{%0,%1,%2,%3}, {%4,%5,%6,%7}, {%8,%9}, {%0,%1,%2,%3};"
        : "+f"(c[0]), "+f"(c[1]), "+f"(c[2]), "+f"(c[3])
        : "r"(a[0]), "r"(a[1]), "r"(a[2]), "r"(a[3]), "r"(b[0]), "r"(b[1]));
}

__device__ __forceinline__ float compute_scale(int slot) {
    float m = __uint_as_float(g_absmax_bits[slot]);
    float s = __fdiv_rn(m, FP8_MAX_F);               // RNE f32 division, matches jnp
    if (slot == 0 && !(m > 0.f)) s = 1.0f;           // jnp.where guard (x only)
    return s;
}

// ---------------- preprocessing ----------------
__global__ void reset_kernel() {
    g_absmax_bits[0] = 0u;
    g_absmax_bits[1] = 0u;
}

__global__ void absmax_both_kernel(const float4* __restrict__ x, const float4* __restrict__ w) {
    int slot = (blockIdx.x >= X_BLOCKS) ? 1 : 0;
    const float4* p = slot ? w : x;
    int n4 = slot ? W_N4 : X_N4;
    int b0 = slot ? X_BLOCKS : 0;
    int nb = slot ? (PRE_BLOCKS - X_BLOCKS) : X_BLOCKS;
    float m = 0.f;
    for (int i = (blockIdx.x - b0) * blockDim.x + threadIdx.x; i < n4; i += nb * blockDim.x) {
        float4 v = p[i];
        m = fmaxf(m, fmaxf(fmaxf(fabsf(v.x), fabsf(v.y)), fmaxf(fabsf(v.z), fabsf(v.w))));
    }
#pragma unroll
    for (int o = 16; o; o >>= 1) m = fmaxf(m, __shfl_xor_sync(0xFFFFFFFFu, m, o));
    if ((threadIdx.x & 31) == 0) atomicMax(&g_absmax_bits[slot], __float_as_uint(m));
}

__device__ __forceinline__ __nv_bfloat16 quant1(float v, float s) {
    float d = __fdiv_rn(v, s);               // RNE f32 division, same as reference
    __nv_fp8_e4m3 q(d);                      // satfinite RNE -> e4m3
    return __float2bfloat16(float(q));       // exact: e4m3 is a subset of bf16
}

__global__ void quant_both_kernel(const float4* __restrict__ x, const float4* __restrict__ w) {
    int slot = (blockIdx.x >= X_BLOCKS) ? 1 : 0;
    const float4* src = slot ? w : x;
    uint2* dst = slot ? (uint2*)g_wq : (uint2*)g_xq;
    int n4 = slot ? W_N4 : X_N4;
    int b0 = slot ? X_BLOCKS : 0;
    int nb = slot ? (PRE_BLOCKS - X_BLOCKS) : X_BLOCKS;
    float s = compute_scale(slot);
    for (int i = (blockIdx.x - b0) * blockDim.x + threadIdx.x; i < n4; i += nb * blockDim.x) {
        float4 v = src[i];
        union { __nv_bfloat16 h[4]; uint2 u; } pk;
        pk.h[0] = quant1(v.x, s);
        pk.h[1] = quant1(v.y, s);
        pk.h[2] = quant1(v.z, s);
        pk.h[3] = quant1(v.w, s);
        dst[i] = pk.u;
    }
}

// ---------------- GEMM kernel (mma.sync bf16, software-pipelined fragments) ----------------
__device__ __forceinline__ void load_stage_off(uint32_t smem_base, uint32_t sOff, int kit,
                                               int m0, int n0, int tid) {
    int k0 = kit * KC;
    {
        uint32_t base = smem_base + sOff;                       // A at stage start
        const __nv_bfloat16* gA = g_xq + (size_t)m0 * K_TOTAL + k0;
#pragma unroll
        for (int q = tid; q < (TILE_M * 8); q += GEMM_THREADS) {
            int r = q >> 3, c = q & 7;
            uint32_t off = (uint32_t)(r * 128 + c * 16);
            cp16(base + SWZ(off), gA + (size_t)r * K_TOTAL + c * 8);
        }
    }
    {
        uint32_t base = smem_base + sOff + A_BYTES;             // B after A
        const __nv_bfloat16* gB = g_wq + (size_t)n0 * K_TOTAL + k0;
#pragma unroll
        for (int q = tid; q < (TILE_N * 8); q += GEMM_THREADS) {
            int r = q >> 3, c = q & 7;
            uint32_t off = (uint32_t)(r * 128 + c * 16);
            cp16(base + SWZ(off), gB + (size_t)r * K_TOTAL + c * 8);
        }
    }
}

// fragment load for one k16 step: addresses are base + literal offsets (+ sOff reg)
#define LOAD_FRAGS(buf, sOffv, kkLit) do {                                     \
    uint32_t _oA = (sOffv) + ((uint32_t)((kkLit) * 32) ^ caxA);                \
    uint32_t _oB = (sOffv) + ((uint32_t)((kkLit) * 32) ^ cbxB);                \
    ldsm_x4(aF[buf][0], aBase + _oA);                                          \
    ldsm_x4(aF[buf][1], aBase + 2048u + _oA);                                  \
    ldsm_x4(&bF[buf][0][0], bBase + _oB);                                      \
    ldsm_x4(&bF[buf][2][0], bBase + 2048u + _oB);                              \
    ldsm_x4(&bF[buf][4][0], bBase + 4096u + _oB);                              \
    ldsm_x4(&bF[buf][6][0], bBase + 6144u + _oB);                              \
} while (0)

#define MMA_ALL(buf) do {                                                      \
    _Pragma("unroll") for (int _i = 0; _i < 2; ++_i)                           \
        _Pragma("unroll") for (int _j = 0; _j < 8; ++_j)                       \
            mma_bf16(c[_i][_j], aF[buf][_i], bF[buf][_j]);                     \
} while (0)

__global__ void __launch_bounds__(GEMM_THREADS, 2)
gemm_kernel(float* __restrict__ out, const float* __restrict__ bias) {
    extern __shared__ char smem[];
    uint32_t smem_base = smem_u32(smem);
    int tid = threadIdx.x;
    int wid = tid >> 5, lane = tid & 31;

    // supertile rasterization: 8 M-blocks tall stripes across all N-blocks
    const int tiles_n = N_TOTAL / TILE_N;   // 32
    const int SUPER = 8;
    int id = blockIdx.x;
    int sid = id / (SUPER * tiles_n);
    int within = id % (SUPER * tiles_n);
    int bm = sid * SUPER + (within % SUPER);
    int bn = within / SUPER;
    int m0 = bm * TILE_M, n0 = bn * TILE_N;

    // warp tiling: 4 warps along M (32 rows each), 2 along N (64 cols each)
    int wm = (wid >> 1) * 32;
    int wn = (wid & 1) * 64;

    float c[2][8][4];
#pragma unroll
    for (int i = 0; i < 2; ++i)
#pragma unroll
        for (int j = 0; j < 8; ++j)
#pragma unroll
            for (int v = 0; v < 4; ++v) c[i][j][v] = 0.f;

    // strength-reduced swizzled LDSM bases:
    //   A row = wm + i*16 + (lane&7) + ((lane>>3)&1)*8, chunk = 2kk + (lane>>4)
    //   addr = smem_base + row*128 + ((kk*32) ^ ((lane>>4)*16 ^ ((row&7)<<4))) + sOff
    int a_row = wm + (lane & 7) + ((lane >> 3) & 1) * 8;
    uint32_t aBase = smem_base + (uint32_t)(a_row * 128);
    uint32_t caxA = (uint32_t)(((lane >> 4) * 16) ^ ((a_row & 7) << 4));
    //   B row = wn + p*16 + ((lane>>4)<<3) + (lane&7), chunk = 2kk + ((lane>>3)&1)
    int b_row = wn + ((lane >> 4) << 3) + (lane & 7);
    uint32_t bBase = smem_base + (uint32_t)A_BYTES + (uint32_t)(b_row * 128);
    uint32_t cbxB = (uint32_t)((((lane >> 3) & 1) * 16) ^ ((b_row & 7) << 4));

    uint32_t aF[2][2][4];
    uint32_t bF[2][8][2];

    // prologue: fill 2 stages, wait stage 0, preload first fragments
    load_stage_off(smem_base, 0, 0, m0, n0, tid);
    cp_commit();
    load_stage_off(smem_base, STAGE_BYTES, 1, m0, n0, tid);
    cp_commit();
    cp_wait<1>();
    __syncthreads();

    uint32_t s0 = 0, s1 = STAGE_BYTES, s2 = 2 * STAGE_BYTES;
    LOAD_FRAGS(0, s0, 0);

    for (int it = 0; it < KITERS; ++it) {
        // kk0: issue next-stage global loads; MMAs of kk0 overlap kk1 LDSMs
        if (it + 2 < KITERS) load_stage_off(smem_base, s2, it + 2, m0, n0, tid);
        cp_commit();
        LOAD_FRAGS(1, s0, 1);
        MMA_ALL(0);
        // kk1
        LOAD_FRAGS(0, s0, 2);
        MMA_ALL(1);
        // kk2
        LOAD_FRAGS(1, s0, 3);
        MMA_ALL(0);
        // kk3: iteration-boundary sync BEFORE last MMA batch, then prefetch next iter's kk0
        cp_wait<1>();          // own groups <= it+1 complete -> stage it+1 data done
        __syncthreads();       // all threads' copies visible; WAR for stage (it-1)%3 overwrite
        if (it + 1 < KITERS) LOAD_FRAGS(0, s1, 0);
        MMA_ALL(1);
        // rotate stage offsets
        uint32_t t = s0; s0 = s1; s1 = s2; s2 = t;
    }

    // epilogue: scale + bias, f32 out
    float scale = compute_scale(0) * compute_scale(1);
    int g = lane >> 2, t = lane & 3;
#pragma unroll
    for (int i = 0; i < 2; ++i) {
        int r0 = m0 + wm + i * 16 + g;
        float* orow0 = out + (size_t)r0 * N_TOTAL;
        float* orow1 = orow0 + (size_t)8 * N_TOTAL;
#pragma unroll
        for (int j = 0; j < 8; ++j) {
            int col = n0 + wn + j * 8 + t * 2;
            float b0 = bias[col], b1 = bias[col + 1];
            float2 v0 = make_float2(c[i][j][0] * scale + b0, c[i][j][1] * scale + b1);
            float2 v1 = make_float2(c[i][j][2] * scale + b0, c[i][j][3] * scale + b1);
            *reinterpret_cast<float2*>(orow0 + col) = v0;
            *reinterpret_cast<float2*>(orow1 + col) = v1;
        }
    }
}

// ---------------- launch (GEMM is launch index 3 -> ncu capture slot) ----------------
extern "C" void kernel_launch(void* const* d_in, const int* in_sizes, int n_in,
                              void* d_out, int out_size) {
    const float *x = nullptr, *W = nullptr, *bias = nullptr;
    for (int i = 0; i < n_in; ++i) {
        if (in_sizes[i] == N_TOTAL) bias = (const float*)d_in[i];
        else if (in_sizes[i] == M_TOTAL * K_TOTAL) x = (const float*)d_in[i];
        else W = (const float*)d_in[i];
    }
    float* out = (float*)d_out;

    reset_kernel<<<1, 1>>>();                                               // 0
    absmax_both_kernel<<<PRE_BLOCKS, 256>>>((const float4*)x, (const float4*)W); // 1
    quant_both_kernel<<<PRE_BLOCKS, 256>>>((const float4*)x, (const float4*)W);  // 2

    cudaFuncSetAttribute(gemm_kernel, cudaFuncAttributeMaxDynamicSharedMemorySize, SMEM_TOTAL);
    int grid = (M_TOTAL / TILE_M) * (N_TOTAL / TILE_N);   // 64 * 32 = 2048
    gemm_kernel<<<grid, GEMM_THREADS, SMEM_TOTAL>>>(out, bias);             // 3
}